// round 4
// baseline (speedup 1.0000x reference)
#include <cuda_runtime.h>

#define NRr 2048
#define NDd 2048
#define NCMc 32
#define THREADS 512
#define GRID_PERSIST 304   // ~2 CTAs per SM on 152-SM GB300

__device__ __forceinline__ float softplus_f(float x) {
    // softplus via MUFU: max(x,0) + log(1 + exp(-|x|)); ample accuracy vs 1e-3
    return fmaxf(x, 0.0f) + __logf(1.0f + __expf(-fabsf(x)));
}

__global__ __launch_bounds__(THREADS, 2)
void rwm_kernel(const float* __restrict__ CM_Alpha,
                const float* __restrict__ Wearing_Alpha,
                const float* __restrict__ Mobility_Alpha,
                const float* __restrict__ RegionR,
                const float* __restrict__ GI_mean,
                const float* __restrict__ GI_sd,
                const float* __restrict__ InitialSize_log,
                const float* __restrict__ noise,
                const float* __restrict__ psi,
                const float* __restrict__ NPIs,
                const float* __restrict__ wear,
                const float* __restrict__ mob,
                float* __restrict__ out)
{
    __shared__ float s_cm[NCMc];
    __shared__ float s_warp[16];
    __shared__ float s_wscan[16];

    const int t    = threadIdx.x;
    const int lane = t & 31;
    const int wid  = t >> 5;

    if (t < NCMc) s_cm[t] = CM_Alpha[t];
    __syncthreads();

    // loop-invariant scalars, computed once per CTA lifetime
    const float wA   = Wearing_Alpha[0];
    const float mA   = Mobility_Alpha[0];
    const float gm   = GI_mean[0];
    const float gs   = GI_sd[0];
    const float gs2  = gs * gs;
    const float gi_beta      = __expf(gm / gs2);
    const float inv_gi_alpha = gs2 / (gm * gm);
    const float rr   = __expf(psi[0]);

    const int d0 = t * 4;

    for (int r = blockIdx.x; r < NRr; r += GRID_PERSIST) {
        const size_t rowOff = (size_t)r * NDd;

        // ---- hot loop: 32 coalesced LDG.128 streams, dual accumulators ----
        float4 acc0 = make_float4(0.f, 0.f, 0.f, 0.f);
        float4 acc1 = make_float4(0.f, 0.f, 0.f, 0.f);
        const float4* np = (const float4*)(NPIs + (size_t)r * NCMc * NDd + d0);
        #pragma unroll
        for (int c = 0; c < NCMc; c += 2) {
            const float4 v0 = np[(size_t)c * (NDd / 4)];
            const float4 v1 = np[(size_t)(c + 1) * (NDd / 4)];
            const float a0 = s_cm[c];
            const float a1 = s_cm[c + 1];
            acc0.x = fmaf(a0, v0.x, acc0.x);
            acc0.y = fmaf(a0, v0.y, acc0.y);
            acc0.z = fmaf(a0, v0.z, acc0.z);
            acc0.w = fmaf(a0, v0.w, acc0.w);
            acc1.x = fmaf(a1, v1.x, acc1.x);
            acc1.y = fmaf(a1, v1.y, acc1.y);
            acc1.z = fmaf(a1, v1.z, acc1.z);
            acc1.w = fmaf(a1, v1.w, acc1.w);
        }
        const float grx = acc0.x + acc1.x;
        const float gry = acc0.y + acc1.y;
        const float grz = acc0.z + acc1.z;
        const float grw = acc0.w + acc1.w;

        const float regR  = RegionR[r];
        const float initL = InitialSize_log[r];
        const float sp0   = softplus_f(mA * __ldg(mob + rowOff));

        const float4 wr = *(const float4*)(wear  + rowOff + d0);
        const float4 mb = *(const float4*)(mob   + rowOff + d0);
        const float4 nz = *(const float4*)(noise + rowOff + d0);

        // per-day growth = gi_beta + exp(ExpectedLogR)/gi_alpha + noise
        float g[4];
        {
            const float grv[4] = {grx, gry, grz, grw};
            const float wv[4]  = {wr.x, wr.y, wr.z, wr.w};
            const float mv[4]  = {mb.x, mb.y, mb.z, mb.w};
            const float nv[4]  = {nz.x, nz.y, nz.z, nz.w};
            #pragma unroll
            for (int k = 0; k < 4; ++k) {
                const float elr = regR - grv[k] - wA * wv[k]
                                - (softplus_f(mA * mv[k]) - sp0);
                g[k] = fmaf(__expf(elr), inv_gi_alpha, gi_beta) + nv[k];
            }
        }

        // thread-local inclusive prefix over the 4 owned days
        const float p1 = g[0];
        const float p2 = p1 + g[1];
        const float p3 = p2 + g[2];
        const float p4 = p3 + g[3];

        // block-wide inclusive scan of per-thread quad sums (16 warps)
        float v = p4;
        #pragma unroll
        for (int o = 1; o < 32; o <<= 1) {
            const float n = __shfl_up_sync(0xffffffffu, v, o);
            if (lane >= o) v += n;
        }
        if (lane == 31) s_warp[wid] = v;
        __syncthreads();
        if (wid == 0) {
            float wv2 = (lane < 16) ? s_warp[lane] : 0.0f;
            #pragma unroll
            for (int o = 1; o < 16; o <<= 1) {
                const float n = __shfl_up_sync(0xffffffffu, wv2, o);
                if (lane >= o) wv2 += n;
            }
            if (lane < 16) s_wscan[lane] = wv2;
        }
        __syncthreads();

        const float warpOff = (wid > 0) ? s_wscan[wid - 1] : 0.0f;
        const float excl = warpOff + (v - p4);   // exclusive prefix

        // p = r / (r + exp(LogInfected)) + 1e-8
        const float base = initL + excl;
        float4 o4;
        o4.x = __fdividef(rr, rr + __expf(base + p1)) + 1e-8f;
        o4.y = __fdividef(rr, rr + __expf(base + p2)) + 1e-8f;
        o4.z = __fdividef(rr, rr + __expf(base + p3)) + 1e-8f;
        o4.w = __fdividef(rr, rr + __expf(base + p4)) + 1e-8f;
        __stcs((float4*)(out + rowOff + d0), o4);

        // barrier so s_warp/s_wscan can be safely overwritten next iteration
        __syncthreads();
    }
}

extern "C" void kernel_launch(void* const* d_in, const int* in_sizes, int n_in,
                              void* d_out, int out_size)
{
    const float* CM_Alpha        = (const float*)d_in[0];
    const float* Wearing_Alpha   = (const float*)d_in[1];
    const float* Mobility_Alpha  = (const float*)d_in[2];
    const float* RegionR         = (const float*)d_in[3];
    const float* GI_mean         = (const float*)d_in[4];
    const float* GI_sd           = (const float*)d_in[5];
    const float* InitialSize_log = (const float*)d_in[6];
    const float* noise           = (const float*)d_in[7];
    const float* psi             = (const float*)d_in[8];
    const float* NPIs            = (const float*)d_in[9];
    const float* wear            = (const float*)d_in[10];
    const float* mobility        = (const float*)d_in[11];
    float* out = (float*)d_out;

    rwm_kernel<<<GRID_PERSIST, THREADS>>>(CM_Alpha, Wearing_Alpha, Mobility_Alpha,
                                          RegionR, GI_mean, GI_sd, InitialSize_log,
                                          noise, psi, NPIs, wear, mobility, out);
}

// round 5
// speedup vs baseline: 1.0484x; 1.0484x over previous
#include <cuda_runtime.h>

#define NRr 2048
#define NDd 2048
#define NCMc 32
#define THREADS 512

__device__ __forceinline__ float softplus_f(float x) {
    // softplus via MUFU: max(x,0) + log(1 + exp(-|x|)); ample accuracy vs 1e-3
    return fmaxf(x, 0.0f) + __logf(1.0f + __expf(-fabsf(x)));
}

__global__ __launch_bounds__(THREADS, 3)
void rwm_kernel(const float* __restrict__ CM_Alpha,
                const float* __restrict__ Wearing_Alpha,
                const float* __restrict__ Mobility_Alpha,
                const float* __restrict__ RegionR,
                const float* __restrict__ GI_mean,
                const float* __restrict__ GI_sd,
                const float* __restrict__ InitialSize_log,
                const float* __restrict__ noise,
                const float* __restrict__ psi,
                const float* __restrict__ NPIs,
                const float* __restrict__ wear,
                const float* __restrict__ mob,
                float* __restrict__ out)
{
    __shared__ float s_cm[NCMc];
    __shared__ float s_warp[16];

    const int r    = blockIdx.x;
    const int t    = threadIdx.x;
    const int lane = t & 31;
    const int wid  = t >> 5;

    if (t < NCMc) s_cm[t] = CM_Alpha[t];
    __syncthreads();

    const size_t rowOff = (size_t)r * NDd;
    const int d0 = t * 4;

    // ---- hot loop first: 32 coalesced streaming LDG.128 reads ----
    float4 gr = make_float4(0.f, 0.f, 0.f, 0.f);
    const float4* np = (const float4*)(NPIs + (size_t)r * NCMc * NDd + d0);
    #pragma unroll
    for (int c = 0; c < NCMc; ++c) {
        const float4 v = __ldcs(np + (size_t)c * (NDd / 4));
        const float a = s_cm[c];
        gr.x = fmaf(a, v.x, gr.x);
        gr.y = fmaf(a, v.y, gr.y);
        gr.z = fmaf(a, v.z, gr.z);
        gr.w = fmaf(a, v.w, gr.w);
    }

    // scalars (broadcast loads) — after the loop to keep hot-loop regs low
    const float wA   = Wearing_Alpha[0];
    const float mA   = Mobility_Alpha[0];
    const float gm   = GI_mean[0];
    const float gs   = GI_sd[0];
    const float gs2  = gs * gs;
    const float gi_beta      = __expf(gm / gs2);
    const float inv_gi_alpha = gs2 / (gm * gm);
    const float rr    = __expf(psi[0]);
    const float regR  = RegionR[r];
    const float initL = InitialSize_log[r];
    const float sp0 = softplus_f(mA * __ldg(mob + rowOff));

    const float4 wr = __ldcs((const float4*)(wear  + rowOff + d0));
    const float4 mb = __ldcs((const float4*)(mob   + rowOff + d0));
    const float4 nz = __ldcs((const float4*)(noise + rowOff + d0));

    // per-day growth = gi_beta + exp(ExpectedLogR)/gi_alpha + noise
    float g[4];
    {
        const float grv[4] = {gr.x, gr.y, gr.z, gr.w};
        const float wv[4]  = {wr.x, wr.y, wr.z, wr.w};
        const float mv[4]  = {mb.x, mb.y, mb.z, mb.w};
        const float nv[4]  = {nz.x, nz.y, nz.z, nz.w};
        #pragma unroll
        for (int k = 0; k < 4; ++k) {
            const float elr = regR - grv[k] - wA * wv[k]
                            - (softplus_f(mA * mv[k]) - sp0);
            g[k] = fmaf(__expf(elr), inv_gi_alpha, gi_beta) + nv[k];
        }
    }

    // thread-local inclusive prefix over the 4 owned days
    const float p1 = g[0];
    const float p2 = p1 + g[1];
    const float p3 = p2 + g[2];
    const float p4 = p3 + g[3];

    // warp-level inclusive scan of per-thread quad sums
    float v = p4;
    #pragma unroll
    for (int o = 1; o < 32; o <<= 1) {
        const float n = __shfl_up_sync(0xffffffffu, v, o);
        if (lane >= o) v += n;
    }
    if (lane == 31) s_warp[wid] = v;
    __syncthreads();

    // single-barrier cross-warp fixup: every warp redundantly scans the 16
    // warp totals in its own lanes, then broadcasts the needed prefix.
    float ws = (lane < 16) ? s_warp[lane] : 0.0f;
    #pragma unroll
    for (int o = 1; o < 16; o <<= 1) {
        const float n = __shfl_up_sync(0xffffffffu, ws, o);
        if (lane >= o) ws += n;
    }
    // exclusive prefix of this warp = inclusive scan value at lane (wid-1)
    const float warpOff = (wid > 0)
        ? __shfl_sync(0xffffffffu, ws, wid - 1) : 0.0f;
    const float excl = warpOff + (v - p4);   // exclusive prefix for this thread

    // p = r / (r + exp(LogInfected)) + 1e-8
    const float base = initL + excl;
    float4 o4;
    o4.x = __fdividef(rr, rr + __expf(base + p1)) + 1e-8f;
    o4.y = __fdividef(rr, rr + __expf(base + p2)) + 1e-8f;
    o4.z = __fdividef(rr, rr + __expf(base + p3)) + 1e-8f;
    o4.w = __fdividef(rr, rr + __expf(base + p4)) + 1e-8f;
    __stcs((float4*)(out + rowOff + d0), o4);
}

extern "C" void kernel_launch(void* const* d_in, const int* in_sizes, int n_in,
                              void* d_out, int out_size)
{
    const float* CM_Alpha        = (const float*)d_in[0];
    const float* Wearing_Alpha   = (const float*)d_in[1];
    const float* Mobility_Alpha  = (const float*)d_in[2];
    const float* RegionR         = (const float*)d_in[3];
    const float* GI_mean         = (const float*)d_in[4];
    const float* GI_sd           = (const float*)d_in[5];
    const float* InitialSize_log = (const float*)d_in[6];
    const float* noise           = (const float*)d_in[7];
    const float* psi             = (const float*)d_in[8];
    const float* NPIs            = (const float*)d_in[9];
    const float* wear            = (const float*)d_in[10];
    const float* mobility        = (const float*)d_in[11];
    float* out = (float*)d_out;

    rwm_kernel<<<NRr, THREADS>>>(CM_Alpha, Wearing_Alpha, Mobility_Alpha,
                                 RegionR, GI_mean, GI_sd, InitialSize_log,
                                 noise, psi, NPIs, wear, mobility, out);
}